// round 16
// baseline (speedup 1.0000x reference)
#include <cuda_runtime.h>
#include <cuda_fp16.h>
#include <mma.h>
#include <math.h>
#include <cstdint>

using namespace nvcuda;

#define NN   100000
#define EE   1600000
#define FIN  256
#define FOUT 128
#define SCAN_BLK 1024
#define NBLK ((NN + SCAN_BLK - 1) / SCAN_BLK)   // 98

// Scratch (static __device__)
__device__ __half g_yh[(size_t)NN * FOUT];    // y = A@W (UNSCALED), fp16
__device__ __half g_Wh[FIN * FOUT];           // W fp16 [k][n]
__device__ int   g_degi[NN];
__device__ float g_dinv[NN];
__device__ int   g_start[NN];
__device__ int   g_cursor[NN];
__device__ int   g_srow[EE];
__device__ int   g_bsum[NBLK];
__device__ float g_hsum[FOUT];
__device__ int   g_ticket;

static __device__ __forceinline__ uint32_t s2u(const void* p) {
    return (uint32_t)__cvta_generic_to_shared(p);
}
static __device__ __forceinline__ void cpasync16(uint32_t dst, const void* src) {
    asm volatile("cp.async.cg.shared.global [%0], [%1], 16;"
                 :: "r"(dst), "l"(src) : "memory");
}

// ---------------------------------------------------------------------------
__global__ void k_zero() {
    int i = blockIdx.x * blockDim.x + threadIdx.x;
    int stride = gridDim.x * blockDim.x;
    for (int j = i; j < NN; j += stride) g_degi[j] = 0;
    if (i < FOUT) g_hsum[i] = 0.0f;
    if (i == 0)   g_ticket = 0;
}

__global__ void k_initW(const float* __restrict__ W) {
    int i = blockIdx.x * blockDim.x + threadIdx.x;
    if (i < FIN * FOUT) g_Wh[i] = __float2half(W[i]);
}

__global__ void k_deg(const int* __restrict__ col, int e) {
    int i = blockIdx.x * blockDim.x + threadIdx.x;
    int base = i * 4;
    if (base + 4 <= e) {
        int4 c = *(const int4*)(col + base);
        atomicAdd(&g_degi[c.x], 1);
        atomicAdd(&g_degi[c.y], 1);
        atomicAdd(&g_degi[c.z], 1);
        atomicAdd(&g_degi[c.w], 1);
    } else {
        for (int j = base; j < e; j++) atomicAdd(&g_degi[col[j]], 1);
    }
}

__global__ void k_scan1() {
    __shared__ int sd[SCAN_BLK];
    int tx = threadIdx.x;
    int i = blockIdx.x * SCAN_BLK + tx;
    int v = (i < NN) ? g_degi[i] : 0;
    if (i < NN) g_dinv[i] = rsqrtf((float)(v + 1));
    sd[tx] = v;
    __syncthreads();
#pragma unroll
    for (int off = 1; off < SCAN_BLK; off <<= 1) {
        int t = (tx >= off) ? sd[tx - off] : 0;
        __syncthreads();
        sd[tx] += t;
        __syncthreads();
    }
    if (i < NN) g_start[i] = sd[tx] - v;
    if (tx == SCAN_BLK - 1) g_bsum[blockIdx.x] = sd[tx];
}

__global__ void k_scan3() {
    __shared__ int sb[128];
    int tx = threadIdx.x;
    if (tx < 128) sb[tx] = (tx < NBLK) ? g_bsum[tx] : 0;
    __syncthreads();
#pragma unroll
    for (int off = 1; off < 128; off <<= 1) {
        int t = 0;
        if (tx < 128 && tx >= off) t = sb[tx - off];
        __syncthreads();
        if (tx < 128) sb[tx] += t;
        __syncthreads();
    }
    int boff = (blockIdx.x == 0) ? 0 : sb[blockIdx.x - 1];
    int i = blockIdx.x * SCAN_BLK + tx;
    if (i < NN) {
        int s = g_start[i] + boff;
        g_start[i]  = s;
        g_cursor[i] = s;
    }
}

__global__ void k_sort(const int* __restrict__ row, const int* __restrict__ col, int e) {
    int i = blockIdx.x * blockDim.x + threadIdx.x;
    if (i < e) {
        int p = atomicAdd(&g_cursor[col[i]], 1);
        g_srow[p] = row[i];
    }
}

// ---------------------------------------------------------------------------
// fp16 GEMM via wmma (R15 version, unchanged). CTA 64x128, 128 threads.
// A converted once into persistent smem; B double-buffered cp.async. 3 CTA/SM.
#define A_LDF  264
#define B_LD   136
#define A_BYTES (64 * A_LDF * 2)              // 33792
#define BBUF   (64 * B_LD * 2)                // 17408
#define B_BASE A_BYTES
#define GEMM_SMEM (B_BASE + 2 * BBUF)         // 68608

__global__ void __launch_bounds__(128, 3)
k_gemm_mma(const float* __restrict__ A, int N) {
    extern __shared__ char sm[];
    __half* As = (__half*)sm;

    const int tx = threadIdx.x;
    const int wid = tx >> 5;
    const int lane = tx & 31;
    const int wr = wid >> 1;
    const int wc = wid & 1;
    const int block_row = blockIdx.x * 64;

    auto load_B = [&](int kc, int buf) {
        uint32_t bs = s2u(sm + B_BASE + buf * BBUF);
#pragma unroll
        for (int it = 0; it < 8; it++) {
            int t = tx + 128 * it;
            int k = t >> 4, ng = t & 15;
            cpasync16(bs + (k * B_LD + ng * 8) * 2,
                      g_Wh + (size_t)(kc * 64 + k) * FOUT + ng * 8);
        }
        asm volatile("cp.async.commit_group;" ::: "memory");
    };

    load_B(0, 0);

    // A prologue: stream 64 rows x 256 k fp32 -> fp16 smem (once)
#pragma unroll
    for (int it = 0; it < 32; it++) {
        int t = tx + 128 * it;
        int r = t >> 6, c4 = t & 63;
        int gr = block_row + r;
        float4 f = make_float4(0.f, 0.f, 0.f, 0.f);
        if (gr < N) f = *(const float4*)(A + (size_t)gr * FIN + c4 * 4);
        __half2 h0 = __float22half2_rn(make_float2(f.x, f.y));
        __half2 h1 = __float22half2_rn(make_float2(f.z, f.w));
        *(uint2*)(As + r * A_LDF + c4 * 4) = make_uint2(*(uint32_t*)&h0, *(uint32_t*)&h1);
    }

    wmma::fragment<wmma::accumulator, 16, 16, 16, float> acc[2][4];
#pragma unroll
    for (int i = 0; i < 2; i++)
#pragma unroll
        for (int j = 0; j < 4; j++) wmma::fill_fragment(acc[i][j], 0.0f);

    __syncthreads();

    for (int kc = 0; kc < 4; kc++) {
        if (kc < 3) {
            load_B(kc + 1, (kc + 1) & 1);
            asm volatile("cp.async.wait_group 1;" ::: "memory");
        } else {
            asm volatile("cp.async.wait_group 0;" ::: "memory");
        }
        __syncthreads();

        const __half* Bs = (const __half*)(sm + B_BASE + (kc & 1) * BBUF);
#pragma unroll
        for (int kk = 0; kk < 4; kk++) {
            wmma::fragment<wmma::matrix_a, 16, 16, 16, __half, wmma::row_major> af[2];
#pragma unroll
            for (int i = 0; i < 2; i++)
                wmma::load_matrix_sync(af[i],
                    As + (wr * 32 + i * 16) * A_LDF + kc * 64 + kk * 16, A_LDF);
#pragma unroll
            for (int j = 0; j < 4; j++) {
                wmma::fragment<wmma::matrix_b, 16, 16, 16, __half, wmma::row_major> bf;
                wmma::load_matrix_sync(bf, Bs + (kk * 16) * B_LD + wc * 64 + j * 16, B_LD);
#pragma unroll
                for (int i = 0; i < 2; i++)
                    wmma::mma_sync(acc[i][j], af[i], bf, acc[i][j]);
            }
        }
        __syncthreads();
    }

    float* stage = (float*)sm + wid * 1088;
#pragma unroll
    for (int i = 0; i < 2; i++) {
#pragma unroll
        for (int j = 0; j < 4; j++)
            wmma::store_matrix_sync(stage + j * 16, acc[i][j], 68, wmma::mem_row_major);
        __syncwarp();
        int rr = lane >> 1;
        int ch = (lane & 1) * 32;
        int grow = block_row + wr * 32 + i * 16 + rr;
        if (grow < N) {
            const float* sp = stage + rr * 68 + ch;
            __half* yp = g_yh + (size_t)grow * FOUT + wc * 64 + ch;
#pragma unroll
            for (int q = 0; q < 4; q++) {
                float4 a = *(const float4*)(sp + q * 8);
                float4 c = *(const float4*)(sp + q * 8 + 4);
                __half2 p0 = __float22half2_rn(make_float2(a.x, a.y));
                __half2 p1 = __float22half2_rn(make_float2(a.z, a.w));
                __half2 p2 = __float22half2_rn(make_float2(c.x, c.y));
                __half2 p3 = __float22half2_rn(make_float2(c.z, c.w));
                *(uint4*)(yp + q * 8) = make_uint4(*(uint32_t*)&p0, *(uint32_t*)&p1,
                                                   *(uint32_t*)&p2, *(uint32_t*)&p3);
            }
        }
        __syncwarp();
    }
}

// ---------------------------------------------------------------------------
// Gather-aggregate: 16 lanes per edge (LDG.128), hi/lo warp halves handle
// even/odd edges; d=0 masks tails; shfl_down(16) merges. One warp per node.
__global__ void __launch_bounds__(256)
k_agg(const float* __restrict__ b, float* __restrict__ out, int N, int E, float ninv) {
    __shared__ float hpart[FOUT];
    __shared__ int is_last;
    const int tx = threadIdx.x;
    if (tx < FOUT) hpart[tx] = 0.0f;
    __syncthreads();

    const int lane = tx & 31;
    const int warp = tx >> 5;
    const int lane16 = lane & 15;
    const int hi = lane >> 4;
    const int node = blockIdx.x * 8 + warp;

    float acc[8];
#pragma unroll
    for (int q = 0; q < 8; q++) acc[q] = 0.0f;

    float dvn = 0.0f;
    if (node < N) {
        dvn = g_dinv[node];
        // self-loop: lo half only (hi half masked), merged later
        {
            uint4 u = *(const uint4*)(g_yh + (size_t)node * FOUT + lane16 * 8);
            float sc = hi ? 0.0f : dvn;
            const __half2* hp = (const __half2*)&u;
#pragma unroll
            for (int q = 0; q < 4; q++) {
                float2 f = __half22float2(hp[q]);
                acc[2 * q + 0] = fmaf(f.x, sc, acc[2 * q + 0]);
                acc[2 * q + 1] = fmaf(f.y, sc, acc[2 * q + 1]);
            }
        }
        int s  = g_start[node];
        int e2 = (node + 1 < N) ? g_start[node + 1] : E;

        for (int base = s; base < e2; base += 32) {
            int cnt = min(32, e2 - base);
            int myidx = (lane < cnt) ? g_srow[base + lane] : 0;
            float mydv = (lane < cnt) ? g_dinv[myidx] : 0.0f;
            for (int j = 0; j < cnt; j += 4) {
                int p0 = j + hi, p1 = j + 2 + hi;
                int r0 = __shfl_sync(0xffffffffu, myidx, p0);
                float d0 = __shfl_sync(0xffffffffu, mydv, p0);
                int r1 = __shfl_sync(0xffffffffu, myidx, p1);
                float d1 = __shfl_sync(0xffffffffu, mydv, p1);
                uint4 u0 = *(const uint4*)(g_yh + (size_t)r0 * FOUT + lane16 * 8);
                uint4 u1 = *(const uint4*)(g_yh + (size_t)r1 * FOUT + lane16 * 8);
                const __half2* h0 = (const __half2*)&u0;
                const __half2* h1 = (const __half2*)&u1;
#pragma unroll
                for (int q = 0; q < 4; q++) {
                    float2 f0 = __half22float2(h0[q]);
                    float2 f1 = __half22float2(h1[q]);
                    acc[2 * q + 0] = fmaf(f0.x, d0, acc[2 * q + 0]);
                    acc[2 * q + 1] = fmaf(f0.y, d0, acc[2 * q + 1]);
                    acc[2 * q + 0] = fmaf(f1.x, d1, acc[2 * q + 0]);
                    acc[2 * q + 1] = fmaf(f1.y, d1, acc[2 * q + 1]);
                }
            }
        }
    }

    // merge odd-edge half into lanes 0-15
#pragma unroll
    for (int q = 0; q < 8; q++)
        acc[q] += __shfl_down_sync(0xffffffffu, acc[q], 16);

    float v[8];
#pragma unroll
    for (int q = 0; q < 8; q++) v[q] = 0.0f;
    if (hi == 0) {
        if (node < N) {
#pragma unroll
            for (int q = 0; q < 8; q++)
                v[q] = fmaxf(fmaf(acc[q], dvn, b[lane16 * 8 + q]), 0.0f);
            float4 o0 = make_float4(v[0], v[1], v[2], v[3]);
            float4 o1 = make_float4(v[4], v[5], v[6], v[7]);
            float* op = out + (size_t)node * FOUT + lane16 * 8;
            *(float4*)op = o0;
            *(float4*)(op + 4) = o1;
        }
#pragma unroll
        for (int q = 0; q < 8; q++)
            atomicAdd(&hpart[lane16 * 8 + q], v[q]);
    }
    __syncthreads();
    if (tx < FOUT) atomicAdd(&g_hsum[tx], hpart[tx]);

    if (tx == 0) {
        __threadfence();
        int t = atomicAdd(&g_ticket, 1);
        is_last = (t == (int)gridDim.x - 1) ? 1 : 0;
    }
    __syncthreads();
    if (is_last) {
        __threadfence();
        if (tx < FOUT) {
            float m = g_hsum[tx] * ninv;
            out[(size_t)N * FOUT + tx] = 1.0f / (1.0f + expf(-m));
        }
    }
}

// ---------------------------------------------------------------------------
extern "C" void kernel_launch(void* const* d_in, const int* in_sizes, int n_in,
                              void* d_out, int out_size) {
    const float* feat = (const float*)d_in[0];
    const int*   ei   = (const int*)d_in[1];
    const float* W    = (const float*)d_in[2];
    const float* b    = (const float*)d_in[3];
    float* out = (float*)d_out;

    int N = in_sizes[0] / FIN;
    int E = in_sizes[1] / 2;
    const int* rowp = ei;
    const int* colp = ei + E;

    static cudaStream_t s2 = nullptr;
    static cudaEvent_t evFork = nullptr, evJoin = nullptr;
    if (!s2) {
        cudaStreamCreateWithFlags(&s2, cudaStreamNonBlocking);
        cudaEventCreateWithFlags(&evFork, cudaEventDisableTiming);
        cudaEventCreateWithFlags(&evJoin, cudaEventDisableTiming);
        cudaFuncSetAttribute(k_gemm_mma, cudaFuncAttributeMaxDynamicSharedMemorySize, GEMM_SMEM);
    }

    cudaEventRecord(evFork, 0);
    cudaStreamWaitEvent(s2, evFork, 0);

    // GEMM at launch index 3 (ncu capture slot).
    k_initW<<<(FIN * FOUT + 255) / 256, 256, 0, s2>>>(W);           // 0
    k_zero<<<392, 256>>>();                                         // 1
    k_deg<<<(E / 4 + 255) / 256, 256>>>(colp, E);                   // 2
    k_gemm_mma<<<(N + 63) / 64, 128, GEMM_SMEM, s2>>>(feat, N);     // 3 <- profiled
    cudaEventRecord(evJoin, s2);

    k_scan1<<<NBLK, SCAN_BLK>>>();                                  // 4
    k_scan3<<<NBLK, SCAN_BLK>>>();                                  // 5
    k_sort<<<(E + 255) / 256, 256>>>(rowp, colp, E);                // 6

    cudaStreamWaitEvent(0, evJoin, 0);
    k_agg<<<(N + 7) / 8, 256>>>(b, out, N, E, 1.0f / (float)N);     // 7
}

// round 17
// speedup vs baseline: 1.1457x; 1.1457x over previous
#include <cuda_runtime.h>
#include <cuda_fp16.h>
#include <mma.h>
#include <math.h>
#include <cstdint>

using namespace nvcuda;

#define NN   100000
#define EE   1600000
#define FIN  256
#define FOUT 128
#define SCAN_BLK 1024
#define NBLK ((NN + SCAN_BLK - 1) / SCAN_BLK)   // 98

// Scratch (static __device__)
__device__ __half g_yh[(size_t)NN * FOUT];    // y = A@W (UNSCALED), fp16
__device__ __half g_Wh[FIN * FOUT];           // W fp16 [k][n]
__device__ int   g_degi[NN];
__device__ float g_dinv[NN];
__device__ int   g_start[NN];
__device__ int   g_cursor[NN];
__device__ int   g_srow[EE];
__device__ int   g_bsum[NBLK];
__device__ float g_hsum[FOUT];
__device__ int   g_ticket;

static __device__ __forceinline__ uint32_t s2u(const void* p) {
    return (uint32_t)__cvta_generic_to_shared(p);
}
static __device__ __forceinline__ void cpasync16(uint32_t dst, const void* src) {
    asm volatile("cp.async.cg.shared.global [%0], [%1], 16;"
                 :: "r"(dst), "l"(src) : "memory");
}

// ---------------------------------------------------------------------------
__global__ void k_zero() {
    int i = blockIdx.x * blockDim.x + threadIdx.x;
    int stride = gridDim.x * blockDim.x;
    for (int j = i; j < NN; j += stride) g_degi[j] = 0;
    if (i < FOUT) g_hsum[i] = 0.0f;
    if (i == 0)   g_ticket = 0;
}

__global__ void k_initW(const float* __restrict__ W) {
    int i = blockIdx.x * blockDim.x + threadIdx.x;
    if (i < FIN * FOUT) g_Wh[i] = __float2half(W[i]);
}

__global__ void k_deg(const int* __restrict__ col, int e) {
    int i = blockIdx.x * blockDim.x + threadIdx.x;
    int base = i * 4;
    if (base + 4 <= e) {
        int4 c = *(const int4*)(col + base);
        atomicAdd(&g_degi[c.x], 1);
        atomicAdd(&g_degi[c.y], 1);
        atomicAdd(&g_degi[c.z], 1);
        atomicAdd(&g_degi[c.w], 1);
    } else {
        for (int j = base; j < e; j++) atomicAdd(&g_degi[col[j]], 1);
    }
}

__global__ void k_scan1() {
    __shared__ int sd[SCAN_BLK];
    int tx = threadIdx.x;
    int i = blockIdx.x * SCAN_BLK + tx;
    int v = (i < NN) ? g_degi[i] : 0;
    if (i < NN) g_dinv[i] = rsqrtf((float)(v + 1));
    sd[tx] = v;
    __syncthreads();
#pragma unroll
    for (int off = 1; off < SCAN_BLK; off <<= 1) {
        int t = (tx >= off) ? sd[tx - off] : 0;
        __syncthreads();
        sd[tx] += t;
        __syncthreads();
    }
    if (i < NN) g_start[i] = sd[tx] - v;
    if (tx == SCAN_BLK - 1) g_bsum[blockIdx.x] = sd[tx];
}

__global__ void k_scan3() {
    __shared__ int sb[128];
    int tx = threadIdx.x;
    if (tx < 128) sb[tx] = (tx < NBLK) ? g_bsum[tx] : 0;
    __syncthreads();
#pragma unroll
    for (int off = 1; off < 128; off <<= 1) {
        int t = 0;
        if (tx < 128 && tx >= off) t = sb[tx - off];
        __syncthreads();
        if (tx < 128) sb[tx] += t;
        __syncthreads();
    }
    int boff = (blockIdx.x == 0) ? 0 : sb[blockIdx.x - 1];
    int i = blockIdx.x * SCAN_BLK + tx;
    if (i < NN) {
        int s = g_start[i] + boff;
        g_start[i]  = s;
        g_cursor[i] = s;
    }
}

__global__ void k_sort(const int* __restrict__ row, const int* __restrict__ col, int e) {
    int i = blockIdx.x * blockDim.x + threadIdx.x;
    if (i < e) {
        int p = atomicAdd(&g_cursor[col[i]], 1);
        g_srow[p] = row[i];
    }
}

// ---------------------------------------------------------------------------
// fp16 GEMM via wmma. CTA 64x128, 128 threads, 3 CTA/SM.
// A converted into persistent smem, pipelined: chunk kc+1 LDGs issue before
// MMAs on chunk kc, conversion stores after. B double-buffered via cp.async.
#define A_LDF  264
#define B_LD   136
#define A_BYTES (64 * A_LDF * 2)              // 33792
#define BBUF   (64 * B_LD * 2)                // 17408
#define B_BASE A_BYTES
#define GEMM_SMEM (B_BASE + 2 * BBUF)         // 68608

__global__ void __launch_bounds__(128, 3)
k_gemm_mma(const float* __restrict__ A, int N) {
    extern __shared__ char sm[];
    __half* As = (__half*)sm;

    const int tx = threadIdx.x;
    const int wid = tx >> 5;
    const int lane = tx & 31;
    const int wr = wid >> 1;
    const int wc = wid & 1;
    const int block_row = blockIdx.x * 64;

    // this thread's fixed (row, float4-col) slots within a 64x64 A chunk
    const int a_r0 = tx >> 1;              // rows: tx/2 and tx/2+... pattern below
    auto a_src = [&](int kc, int it) {     // it in 0..7 -> 8 float4 per thread
        int t = tx + 128 * it;             // 0..1023
        int r = t >> 4, c4 = t & 15;
        int gr = block_row + r;
        return (gr < N) ? (A + (size_t)gr * FIN + kc * 64 + c4 * 4) : (const float*)nullptr;
    };
    auto a_dst = [&](int kc, int it) {
        int t = tx + 128 * it;
        int r = t >> 4, c4 = t & 15;
        return As + r * A_LDF + kc * 64 + c4 * 4;
    };
    (void)a_r0;

    auto load_B = [&](int kc, int buf) {
        uint32_t bs = s2u(sm + B_BASE + buf * BBUF);
#pragma unroll
        for (int it = 0; it < 8; it++) {
            int t = tx + 128 * it;
            int k = t >> 4, ng = t & 15;
            cpasync16(bs + (k * B_LD + ng * 8) * 2,
                      g_Wh + (size_t)(kc * 64 + k) * FOUT + ng * 8);
        }
        asm volatile("cp.async.commit_group;" ::: "memory");
    };

    load_B(0, 0);

    // prologue: chunk 0 only (load + convert, 16 KB)
#pragma unroll
    for (int it = 0; it < 8; it++) {
        const float* sp = a_src(0, it);
        float4 f = sp ? *(const float4*)sp : make_float4(0.f, 0.f, 0.f, 0.f);
        __half2 h0 = __float22half2_rn(make_float2(f.x, f.y));
        __half2 h1 = __float22half2_rn(make_float2(f.z, f.w));
        *(uint2*)a_dst(0, it) = make_uint2(*(uint32_t*)&h0, *(uint32_t*)&h1);
    }

    wmma::fragment<wmma::accumulator, 16, 16, 16, float> acc[2][4];
#pragma unroll
    for (int i = 0; i < 2; i++)
#pragma unroll
        for (int j = 0; j < 4; j++) wmma::fill_fragment(acc[i][j], 0.0f);

    __syncthreads();

    for (int kc = 0; kc < 4; kc++) {
        // issue A loads for next chunk (independent, hide under MMAs)
        float4 f[8];
        if (kc < 3) {
#pragma unroll
            for (int it = 0; it < 8; it++) {
                const float* sp = a_src(kc + 1, it);
                f[it] = sp ? *(const float4*)sp : make_float4(0.f, 0.f, 0.f, 0.f);
            }
            load_B(kc + 1, (kc + 1) & 1);
            asm volatile("cp.async.wait_group 1;" ::: "memory");
        } else {
            asm volatile("cp.async.wait_group 0;" ::: "memory");
        }
        __syncthreads();

        const __half* Bs = (const __half*)(sm + B_BASE + (kc & 1) * BBUF);
#pragma unroll
        for (int kk = 0; kk < 4; kk++) {
            wmma::fragment<wmma::matrix_a, 16, 16, 16, __half, wmma::row_major> af[2];
#pragma unroll
            for (int i = 0; i < 2; i++)
                wmma::load_matrix_sync(af[i],
                    As + (wr * 32 + i * 16) * A_LDF + kc * 64 + kk * 16, A_LDF);
#pragma unroll
            for (int j = 0; j < 4; j++) {
                wmma::fragment<wmma::matrix_b, 16, 16, 16, __half, wmma::row_major> bf;
                wmma::load_matrix_sync(bf, Bs + (kk * 16) * B_LD + wc * 64 + j * 16, B_LD);
#pragma unroll
                for (int i = 0; i < 2; i++)
                    wmma::mma_sync(acc[i][j], af[i], bf, acc[i][j]);
            }
        }

        // convert + store next A chunk (its smem region is idle this iteration)
        if (kc < 3) {
#pragma unroll
            for (int it = 0; it < 8; it++) {
                __half2 h0 = __float22half2_rn(make_float2(f[it].x, f[it].y));
                __half2 h1 = __float22half2_rn(make_float2(f[it].z, f[it].w));
                *(uint2*)a_dst(kc + 1, it) = make_uint2(*(uint32_t*)&h0, *(uint32_t*)&h1);
            }
        }
        __syncthreads();
    }

    // Epilogue: per-warp 16x68 stage (reuses A smem, 4 warps x 4352 B)
    float* stage = (float*)sm + wid * 1088;
#pragma unroll
    for (int i = 0; i < 2; i++) {
#pragma unroll
        for (int j = 0; j < 4; j++)
            wmma::store_matrix_sync(stage + j * 16, acc[i][j], 68, wmma::mem_row_major);
        __syncwarp();
        int rr = lane >> 1;
        int ch = (lane & 1) * 32;
        int grow = block_row + wr * 32 + i * 16 + rr;
        if (grow < N) {
            const float* sp = stage + rr * 68 + ch;
            __half* yp = g_yh + (size_t)grow * FOUT + wc * 64 + ch;
#pragma unroll
            for (int q = 0; q < 4; q++) {
                float4 a = *(const float4*)(sp + q * 8);
                float4 c = *(const float4*)(sp + q * 8 + 4);
                __half2 p0 = __float22half2_rn(make_float2(a.x, a.y));
                __half2 p1 = __float22half2_rn(make_float2(a.z, a.w));
                __half2 p2 = __float22half2_rn(make_float2(c.x, c.y));
                __half2 p3 = __float22half2_rn(make_float2(c.z, c.w));
                *(uint4*)(yp + q * 8) = make_uint4(*(uint32_t*)&p0, *(uint32_t*)&p1,
                                                   *(uint32_t*)&p2, *(uint32_t*)&p3);
            }
        }
        __syncwarp();
    }
}

// ---------------------------------------------------------------------------
// Gather-aggregate (R15 version: 32-lane uint2 loads, gathered dinv, 4-edge unroll).
static __device__ __forceinline__ float4 ldy4(const __half* base, int lane) {
    uint2 u = ((const uint2*)base)[lane];
    __half2 p0 = *(__half2*)&u.x;
    __half2 p1 = *(__half2*)&u.y;
    float2 f0 = __half22float2(p0);
    float2 f1 = __half22float2(p1);
    return make_float4(f0.x, f0.y, f1.x, f1.y);
}

__global__ void __launch_bounds__(256)
k_agg(const float* __restrict__ b, float* __restrict__ out, int N, int E, float ninv) {
    __shared__ float hpart[FOUT];
    __shared__ int is_last;
    const int tx = threadIdx.x;
    if (tx < FOUT) hpart[tx] = 0.0f;
    __syncthreads();

    const int lane = tx & 31;
    const int warp = tx >> 5;
    const int node = blockIdx.x * 8 + warp;

    float4 v = make_float4(0.f, 0.f, 0.f, 0.f);
    if (node < N) {
        float dvn = g_dinv[node];
        float4 sv = ldy4(g_yh + (size_t)node * FOUT, lane);
        float4 acc = make_float4(sv.x * dvn, sv.y * dvn, sv.z * dvn, sv.w * dvn);
        int s  = g_start[node];
        int e2 = (node + 1 < N) ? g_start[node + 1] : E;

        for (int base = s; base < e2; base += 32) {
            int cnt = min(32, e2 - base);
            int myidx = (lane < cnt) ? g_srow[base + lane] : 0;
            float mydv = (lane < cnt) ? g_dinv[myidx] : 0.0f;
            int j = 0;
            for (; j + 4 <= cnt; j += 4) {
                int r0 = __shfl_sync(0xffffffffu, myidx, j + 0);
                int r1 = __shfl_sync(0xffffffffu, myidx, j + 1);
                int r2 = __shfl_sync(0xffffffffu, myidx, j + 2);
                int r3 = __shfl_sync(0xffffffffu, myidx, j + 3);
                float d0 = __shfl_sync(0xffffffffu, mydv, j + 0);
                float d1 = __shfl_sync(0xffffffffu, mydv, j + 1);
                float d2 = __shfl_sync(0xffffffffu, mydv, j + 2);
                float d3 = __shfl_sync(0xffffffffu, mydv, j + 3);
                float4 v0 = ldy4(g_yh + (size_t)r0 * FOUT, lane);
                float4 v1 = ldy4(g_yh + (size_t)r1 * FOUT, lane);
                float4 v2 = ldy4(g_yh + (size_t)r2 * FOUT, lane);
                float4 v3 = ldy4(g_yh + (size_t)r3 * FOUT, lane);
                acc.x = fmaf(v0.x, d0, acc.x); acc.y = fmaf(v0.y, d0, acc.y);
                acc.z = fmaf(v0.z, d0, acc.z); acc.w = fmaf(v0.w, d0, acc.w);
                acc.x = fmaf(v1.x, d1, acc.x); acc.y = fmaf(v1.y, d1, acc.y);
                acc.z = fmaf(v1.z, d1, acc.z); acc.w = fmaf(v1.w, d1, acc.w);
                acc.x = fmaf(v2.x, d2, acc.x); acc.y = fmaf(v2.y, d2, acc.y);
                acc.z = fmaf(v2.z, d2, acc.z); acc.w = fmaf(v2.w, d2, acc.w);
                acc.x = fmaf(v3.x, d3, acc.x); acc.y = fmaf(v3.y, d3, acc.y);
                acc.z = fmaf(v3.z, d3, acc.z); acc.w = fmaf(v3.w, d3, acc.w);
            }
            for (; j < cnt; j++) {
                int r = __shfl_sync(0xffffffffu, myidx, j);
                float dvr = __shfl_sync(0xffffffffu, mydv, j);
                float4 vv = ldy4(g_yh + (size_t)r * FOUT, lane);
                acc.x = fmaf(vv.x, dvr, acc.x);
                acc.y = fmaf(vv.y, dvr, acc.y);
                acc.z = fmaf(vv.z, dvr, acc.z);
                acc.w = fmaf(vv.w, dvr, acc.w);
            }
        }

        float4 bv = ((const float4*)b)[lane];
        v.x = fmaxf(fmaf(acc.x, dvn, bv.x), 0.0f);
        v.y = fmaxf(fmaf(acc.y, dvn, bv.y), 0.0f);
        v.z = fmaxf(fmaf(acc.z, dvn, bv.z), 0.0f);
        v.w = fmaxf(fmaf(acc.w, dvn, bv.w), 0.0f);
        ((float4*)(out + (size_t)node * FOUT))[lane] = v;
    }

    atomicAdd(&hpart[lane * 4 + 0], v.x);
    atomicAdd(&hpart[lane * 4 + 1], v.y);
    atomicAdd(&hpart[lane * 4 + 2], v.z);
    atomicAdd(&hpart[lane * 4 + 3], v.w);
    __syncthreads();
    if (tx < FOUT) atomicAdd(&g_hsum[tx], hpart[tx]);

    if (tx == 0) {
        __threadfence();
        int t = atomicAdd(&g_ticket, 1);
        is_last = (t == (int)gridDim.x - 1) ? 1 : 0;
    }
    __syncthreads();
    if (is_last) {
        __threadfence();
        if (tx < FOUT) {
            float m = g_hsum[tx] * ninv;
            out[(size_t)N * FOUT + tx] = 1.0f / (1.0f + expf(-m));
        }
    }
}

// ---------------------------------------------------------------------------
extern "C" void kernel_launch(void* const* d_in, const int* in_sizes, int n_in,
                              void* d_out, int out_size) {
    const float* feat = (const float*)d_in[0];
    const int*   ei   = (const int*)d_in[1];
    const float* W    = (const float*)d_in[2];
    const float* b    = (const float*)d_in[3];
    float* out = (float*)d_out;

    int N = in_sizes[0] / FIN;
    int E = in_sizes[1] / 2;
    const int* rowp = ei;
    const int* colp = ei + E;

    static cudaStream_t s2 = nullptr;
    static cudaEvent_t evFork = nullptr, evJoin = nullptr;
    if (!s2) {
        cudaStreamCreateWithFlags(&s2, cudaStreamNonBlocking);
        cudaEventCreateWithFlags(&evFork, cudaEventDisableTiming);
        cudaEventCreateWithFlags(&evJoin, cudaEventDisableTiming);
        cudaFuncSetAttribute(k_gemm_mma, cudaFuncAttributeMaxDynamicSharedMemorySize, GEMM_SMEM);
    }

    cudaEventRecord(evFork, 0);
    cudaStreamWaitEvent(s2, evFork, 0);

    // GEMM at launch index 3 (ncu capture slot).
    k_initW<<<(FIN * FOUT + 255) / 256, 256, 0, s2>>>(W);           // 0
    k_zero<<<392, 256>>>();                                         // 1
    k_deg<<<(E / 4 + 255) / 256, 256>>>(colp, E);                   // 2
    k_gemm_mma<<<(N + 63) / 64, 128, GEMM_SMEM, s2>>>(feat, N);     // 3 <- profiled
    cudaEventRecord(evJoin, s2);

    k_scan1<<<NBLK, SCAN_BLK>>>();                                  // 4
    k_scan3<<<NBLK, SCAN_BLK>>>();                                  // 5
    k_sort<<<(E + 255) / 256, 256>>>(rowp, colp, E);                // 6

    cudaStreamWaitEvent(0, evJoin, 0);
    k_agg<<<(N + 7) / 8, 256>>>(b, out, N, E, 1.0f / (float)N);     // 7
}